// round 2
// baseline (speedup 1.0000x reference)
#include <cuda_runtime.h>

// Problem constants
#define NB   4
#define SS   512
#define DD   64
#define NH   8
#define DHH  8
#define DFF_ 256
#define NROWS (NB*SS)      // 2048
#define DT_F 0.25f

// Persistent device scratch (no allocations allowed)
__device__ float g_y[NROWS*DD];
__device__ float g_ytmp[NROWS*DD];
__device__ float g_kstage[6][NROWS*DD];
__device__ float g_q[NB*NH*SS*DHH];
__device__ float g_kk[NB*NH*SS*DHH];
__device__ float g_vv[NB*NH*SS*DHH];
__device__ float g_att[NROWS*DD];

struct Combo  { float c[5]; int n; };
struct FinalC { float c[6]; };

// ---------------------------------------------------------------------------
__global__ void __launch_bounds__(256) copy_in_kernel(const float* __restrict__ x) {
    int i = blockIdx.x * blockDim.x + threadIdx.x;   // 32768 float4
    ((float4*)g_y)[i] = ((const float4*)x)[i];
}
__global__ void __launch_bounds__(256) copy_out_kernel(float* __restrict__ out) {
    int i = blockIdx.x * blockDim.x + threadIdx.x;
    ((float4*)out)[i] = ((const float4*)g_y)[i];
}

// ---------------------------------------------------------------------------
// Kernel A: ytmp = y + DT*sum(c_i * k_i); q,k,v = ytmp @ Wq/Wk/Wv + bias.
// 128 threads = 4 warps, each warp handles 4 rows. 128 blocks -> 2048 rows.
__global__ void __launch_bounds__(128) qkv_kernel(
    const float* __restrict__ Wq, const float* __restrict__ bq,
    const float* __restrict__ Wk, const float* __restrict__ bk,
    const float* __restrict__ Wv, const float* __restrict__ bv,
    Combo cmb)
{
    const int lane = threadIdx.x & 31;
    const int warp = threadIdx.x >> 5;
    const int wg   = blockIdx.x * 4 + warp;   // 0..511
    const int r0   = wg * 4;
    const int j0   = lane * 2;

    // --- RK linear combination (also written to g_ytmp) ---
    float x[4][2];
#pragma unroll
    for (int rr = 0; rr < 4; rr++) {
#pragma unroll
        for (int p = 0; p < 2; p++) {
            int idx = (r0 + rr) * DD + lane + 32 * p;
            float v = g_y[idx];
            for (int c = 0; c < cmb.n; c++) v += cmb.c[c] * g_kstage[c][idx];
            g_ytmp[idx] = v;
            x[rr][p] = v;
        }
    }

    float aq[4][2], ak[4][2], av[4][2];
#pragma unroll
    for (int rr = 0; rr < 4; rr++) {
        aq[rr][0] = aq[rr][1] = 0.f;
        ak[rr][0] = ak[rr][1] = 0.f;
        av[rr][0] = av[rr][1] = 0.f;
    }

    // --- GEMV: lane owns output columns {2*lane, 2*lane+1} of q,k,v ---
#pragma unroll
    for (int p = 0; p < 2; p++) {
#pragma unroll 8
        for (int ii = 0; ii < 32; ii++) {
            const int i = p * 32 + ii;
            float2 wq = *(const float2*)(Wq + i * DD + j0);
            float2 wk = *(const float2*)(Wk + i * DD + j0);
            float2 wv = *(const float2*)(Wv + i * DD + j0);
#pragma unroll
            for (int rr = 0; rr < 4; rr++) {
                float xi = __shfl_sync(0xffffffffu, x[rr][p], ii);
                aq[rr][0] += xi * wq.x; aq[rr][1] += xi * wq.y;
                ak[rr][0] += xi * wk.x; ak[rr][1] += xi * wk.y;
                av[rr][0] += xi * wv.x; av[rr][1] += xi * wv.y;
            }
        }
    }

    const float scale = 0.35355339059327373f;   // 1/sqrt(8)
    float2 bq2 = *(const float2*)(bq + j0);
    float2 bk2 = *(const float2*)(bk + j0);
    float2 bv2 = *(const float2*)(bv + j0);

    const int hh = j0 >> 3;
    const int jj = j0 & 7;
#pragma unroll
    for (int rr = 0; rr < 4; rr++) {
        int r = r0 + rr;
        int b = r >> 9;          // /512
        int s = r & 511;
        int base = ((b * NH + hh) * SS + s) * DHH + jj;
        *(float2*)(g_q  + base) = make_float2((aq[rr][0] + bq2.x) * scale,
                                              (aq[rr][1] + bq2.y) * scale);
        *(float2*)(g_kk + base) = make_float2(ak[rr][0] + bk2.x, ak[rr][1] + bk2.y);
        *(float2*)(g_vv + base) = make_float2(av[rr][0] + bv2.x, av[rr][1] + bv2.y);
    }
}

// ---------------------------------------------------------------------------
// Kernel B: attention. Block = (b,h, qtile of 128 queries), 256 threads.
// 2 threads per query (key halves split by lane bit 4), merged via shfl_xor(16).
__global__ void __launch_bounds__(256) attn_kernel()
{
    __shared__ float4 ks[SS * 2];
    __shared__ float4 vs[SS * 2];

    const int bh  = blockIdx.x >> 2;    // 0..31
    const int qt  = blockIdx.x & 3;
    const int tid = threadIdx.x;

    const float4* kg = (const float4*)g_kk + bh * SS * 2;
    const float4* vg = (const float4*)g_vv + bh * SS * 2;
    for (int i = tid; i < SS * 2; i += 256) { ks[i] = kg[i]; vs[i] = vg[i]; }
    __syncthreads();

    const int lane = tid & 31;
    const int warp = tid >> 5;
    const int half = lane >> 4;
    const int qg   = qt * 128 + warp * 16 + (lane & 15);

    const float4* qp = (const float4*)g_q + (bh * SS + qg) * 2;
    const float4 q0 = qp[0];
    const float4 q1 = qp[1];

    float m = -1e30f, l = 0.f;
    float o[8];
#pragma unroll
    for (int j = 0; j < 8; j++) o[j] = 0.f;

    const int t0 = half * 256;
#pragma unroll 2
    for (int i = 0; i < 256; i++) {
        const int t = t0 + i;
        float4 ka = ks[2 * t], kb = ks[2 * t + 1];
        float s = q0.x * ka.x + q0.y * ka.y + q0.z * ka.z + q0.w * ka.w
                + q1.x * kb.x + q1.y * kb.y + q1.z * kb.z + q1.w * kb.w;
        if (s > m) {
            float corr = __expf(m - s);
            l *= corr;
#pragma unroll
            for (int j = 0; j < 8; j++) o[j] *= corr;
            m = s;
        }
        float p = __expf(s - m);
        l += p;
        float4 va = vs[2 * t], vb = vs[2 * t + 1];
        o[0] += p * va.x; o[1] += p * va.y; o[2] += p * va.z; o[3] += p * va.w;
        o[4] += p * vb.x; o[5] += p * vb.y; o[6] += p * vb.z; o[7] += p * vb.w;
    }

    // merge the two key-halves (lanes l and l^16 share a query)
    float m2 = __shfl_xor_sync(0xffffffffu, m, 16);
    float l2 = __shfl_xor_sync(0xffffffffu, l, 16);
    float M  = fmaxf(m, m2);
    float sA = __expf(m - M);
    float sB = __expf(m2 - M);
    float L  = l * sA + l2 * sB;
    float inv = 1.f / L;

    float res[8];
#pragma unroll
    for (int j = 0; j < 8; j++) {
        float o2 = __shfl_xor_sync(0xffffffffu, o[j], 16);
        res[j] = (o[j] * sA + o2 * sB) * inv;
    }

    if (half == 0) {
        const int b = bh >> 3, h = bh & 7;
        float* dst = g_att + (b * SS + qg) * DD + h * DHH;
        *(float4*)(dst)     = make_float4(res[0], res[1], res[2], res[3]);
        *(float4*)(dst + 4) = make_float4(res[4], res[5], res[6], res[7]);
    }
}

// ---------------------------------------------------------------------------
// Kernel C: att_proj = att_heads @ Wo + bo; h = ytmp + att_proj;
// ffn = relu(h@W1+b1)@W2 + b2; k_stage = att_proj + ffn.
// 256 threads = 8 warps, each warp handles 2 rows. 128 blocks -> 2048 rows.
__global__ void __launch_bounds__(256) ffn_kernel(
    const float* __restrict__ Wo, const float* __restrict__ bo,
    const float* __restrict__ W1, const float* __restrict__ b1,
    const float* __restrict__ W2, const float* __restrict__ b2,
    int stage)
{
    const int lane = threadIdx.x & 31;
    const int warp = threadIdx.x >> 5;
    const int wg   = blockIdx.x * 8 + warp;  // 0..1023
    const int r0   = wg * 2;
    const int j0   = lane * 2;

    // load att rows (lane owns elements {2*lane, 2*lane+1})
    float a[2][2];
#pragma unroll
    for (int rr = 0; rr < 2; rr++) {
        float2 t = *(const float2*)(g_att + (r0 + rr) * DD + j0);
        a[rr][0] = t.x; a[rr][1] = t.y;
    }

    // out projection
    float o1[2][2] = {{0.f,0.f},{0.f,0.f}};
#pragma unroll
    for (int p = 0; p < 2; p++) {
#pragma unroll 8
        for (int ii = 0; ii < 32; ii++) {
            const int i = 2 * ii + p;      // owner lane ii, slot p
            float2 wo = *(const float2*)(Wo + i * DD + j0);
#pragma unroll
            for (int rr = 0; rr < 2; rr++) {
                float ai = __shfl_sync(0xffffffffu, a[rr][p], ii);
                o1[rr][0] += ai * wo.x; o1[rr][1] += ai * wo.y;
            }
        }
    }
    float2 bo2 = *(const float2*)(bo + j0);
    float h[2][2];
#pragma unroll
    for (int rr = 0; rr < 2; rr++) {
        float2 yt = *(const float2*)(g_ytmp + (r0 + rr) * DD + j0);
        o1[rr][0] += bo2.x; o1[rr][1] += bo2.y;
        h[rr][0] = yt.x + o1[rr][0];
        h[rr][1] = yt.y + o1[rr][1];
    }

    // hidden layer: lane owns f = 8*lane .. 8*lane+7
    float u[2][8];
#pragma unroll
    for (int rr = 0; rr < 2; rr++)
#pragma unroll
        for (int j = 0; j < 8; j++) u[rr][j] = 0.f;

#pragma unroll
    for (int p = 0; p < 2; p++) {
#pragma unroll 4
        for (int ii = 0; ii < 32; ii++) {
            const int i = 2 * ii + p;
            float4 w1a = *(const float4*)(W1 + i * DFF_ + lane * 8);
            float4 w1b = *(const float4*)(W1 + i * DFF_ + lane * 8 + 4);
#pragma unroll
            for (int rr = 0; rr < 2; rr++) {
                float hi = __shfl_sync(0xffffffffu, h[rr][p], ii);
                u[rr][0] += hi * w1a.x; u[rr][1] += hi * w1a.y;
                u[rr][2] += hi * w1a.z; u[rr][3] += hi * w1a.w;
                u[rr][4] += hi * w1b.x; u[rr][5] += hi * w1b.y;
                u[rr][6] += hi * w1b.z; u[rr][7] += hi * w1b.w;
            }
        }
    }
    float4 b1a = *(const float4*)(b1 + lane * 8);
    float4 b1b = *(const float4*)(b1 + lane * 8 + 4);
#pragma unroll
    for (int rr = 0; rr < 2; rr++) {
        u[rr][0] = fmaxf(u[rr][0] + b1a.x, 0.f);
        u[rr][1] = fmaxf(u[rr][1] + b1a.y, 0.f);
        u[rr][2] = fmaxf(u[rr][2] + b1a.z, 0.f);
        u[rr][3] = fmaxf(u[rr][3] + b1a.w, 0.f);
        u[rr][4] = fmaxf(u[rr][4] + b1b.x, 0.f);
        u[rr][5] = fmaxf(u[rr][5] + b1b.y, 0.f);
        u[rr][6] = fmaxf(u[rr][6] + b1b.z, 0.f);
        u[rr][7] = fmaxf(u[rr][7] + b1b.w, 0.f);
    }

    // second FFN layer
    float f2[2][2] = {{0.f,0.f},{0.f,0.f}};
#pragma unroll 2
    for (int fo = 0; fo < 32; fo++) {
#pragma unroll
        for (int fi = 0; fi < 8; fi++) {
            const int f = fo * 8 + fi;
            float2 w2 = *(const float2*)(W2 + f * DD + j0);
#pragma unroll
            for (int rr = 0; rr < 2; rr++) {
                float uf = __shfl_sync(0xffffffffu, u[rr][fi], fo);
                f2[rr][0] += uf * w2.x; f2[rr][1] += uf * w2.y;
            }
        }
    }

    float2 b22 = *(const float2*)(b2 + j0);
    float* dst = g_kstage[stage];
#pragma unroll
    for (int rr = 0; rr < 2; rr++) {
        *(float2*)(dst + (r0 + rr) * DD + j0) =
            make_float2(o1[rr][0] + f2[rr][0] + b22.x,
                        o1[rr][1] + f2[rr][1] + b22.y);
    }
}

// ---------------------------------------------------------------------------
__global__ void __launch_bounds__(256) update_kernel(FinalC fc)
{
    int i = blockIdx.x * blockDim.x + threadIdx.x;   // 131072 elems
    float v = g_y[i];
#pragma unroll
    for (int c = 0; c < 6; c++) v += fc.c[c] * g_kstage[c][i];
    g_y[i] = v;
}

// ---------------------------------------------------------------------------
extern "C" void kernel_launch(void* const* d_in, const int* in_sizes, int n_in,
                              void* d_out, int out_size)
{
    (void)in_sizes; (void)n_in; (void)out_size;

    const float* x  = (const float*)d_in[0];
    // d_in[1] = mask: broadcasts over the key axis -> softmax-invariant; ignored.
    const float* Wq = (const float*)d_in[2];
    const float* bq = (const float*)d_in[3];
    const float* Wk = (const float*)d_in[4];
    const float* bk = (const float*)d_in[5];
    const float* Wv = (const float*)d_in[6];
    const float* bv = (const float*)d_in[7];
    const float* Wo = (const float*)d_in[8];
    const float* bo = (const float*)d_in[9];
    const float* W1 = (const float*)d_in[10];
    const float* b1 = (const float*)d_in[11];
    const float* W2 = (const float*)d_in[12];
    const float* b2 = (const float*)d_in[13];

    copy_in_kernel<<<128, 256>>>(x);

    static const double acoef[6][5] = {
        {0, 0, 0, 0, 0},
        {0.25, 0, 0, 0, 0},
        {3.0/32.0, 9.0/32.0, 0, 0, 0},
        {1932.0/2197.0, -7200.0/2197.0, 7296.0/2197.0, 0, 0},
        {439.0/216.0, -8.0, 3680.0/513.0, -845.0/4104.0, 0},
        {-8.0/27.0, 2.0, -3544.0/2565.0, 1859.0/4104.0, -11.0/40.0},
    };
    static const double bcoef[6] = {
        16.0/135.0, 0.0, 6656.0/12825.0, 28561.0/56430.0, -9.0/50.0, 2.0/55.0
    };

    for (int step = 0; step < 4; step++) {
        for (int st = 0; st < 6; st++) {
            Combo cmb;
            cmb.n = st;
            for (int c = 0; c < 5; c++)
                cmb.c[c] = (float)((double)DT_F * acoef[st][c]);
            qkv_kernel<<<128, 128>>>(Wq, bq, Wk, bk, Wv, bv, cmb);
            attn_kernel<<<128, 256>>>();
            ffn_kernel<<<128, 256>>>(Wo, bo, W1, b1, W2, b2, st);
        }
        FinalC fc;
        for (int c = 0; c < 6; c++)
            fc.c[c] = (float)((double)DT_F * bcoef[c]);
        update_kernel<<<512, 256>>>(fc);
    }

    copy_out_kernel<<<128, 256>>>((float*)d_out);
}

// round 3
// speedup vs baseline: 1.2226x; 1.2226x over previous
#include <cuda_runtime.h>

#define NB   4
#define SS   512
#define DD   64
#define NH   8
#define NROWS (NB*SS)      // 2048
#define DT_F 0.25f

// Persistent device scratch (no allocations allowed)
__device__ float g_y[NROWS*DD];
__device__ float g_ytmp[NROWS*DD];
__device__ float g_kst[6*NROWS*DD];
__device__ float g_q[NROWS*DD];
__device__ float g_kk[NROWS*DD];
__device__ float g_vv[NROWS*DD];
__device__ float g_att[NROWS*DD];

struct StageCtl {
    float ac[6];
    int   nc;       // stages to combine (0 = skip combo+qkv tail use)
    int   stage;    // k-slot to write
    int   do_qkv;   // compute qkv of combined state
    int   write_y;  // final combination writes g_y
};

// ---------------------------------------------------------------------------
__global__ void __launch_bounds__(256) copy_out_kernel(float* __restrict__ out) {
    int i = blockIdx.x * blockDim.x + threadIdx.x;
    ((float4*)out)[i] = ((const float4*)g_y)[i];
}

// ---------------------------------------------------------------------------
// qkv GEMV off warp-local smem activations sX (8 rows x 64).
// Mapping: warp rg owns rows {2rg, 2rg+1}; lane owns cols {2*(tid&31), +1}.
__device__ __forceinline__ void qkv_phase(
    const float* sX, int r0,
    const float* __restrict__ Wq, const float* __restrict__ bq,
    const float* __restrict__ Wk, const float* __restrict__ bk,
    const float* __restrict__ Wv, const float* __restrict__ bv)
{
    const int tid = threadIdx.x;
    const int jc = (tid & 31) * 2;
    const int rg = tid >> 5;
    const float* x0p = sX + (2 * rg) * 64;
    const float* x1p = sX + (2 * rg + 1) * 64;

    float aq[2][2] = {{0.f,0.f},{0.f,0.f}};
    float ak[2][2] = {{0.f,0.f},{0.f,0.f}};
    float av[2][2] = {{0.f,0.f},{0.f,0.f}};
#pragma unroll 8
    for (int i = 0; i < 64; i++) {
        float2 wq = __ldg((const float2*)(Wq + i * 64 + jc));
        float2 wk = __ldg((const float2*)(Wk + i * 64 + jc));
        float2 wv = __ldg((const float2*)(Wv + i * 64 + jc));
        float x0 = x0p[i], x1 = x1p[i];
        aq[0][0] += x0 * wq.x; aq[0][1] += x0 * wq.y;
        aq[1][0] += x1 * wq.x; aq[1][1] += x1 * wq.y;
        ak[0][0] += x0 * wk.x; ak[0][1] += x0 * wk.y;
        ak[1][0] += x1 * wk.x; ak[1][1] += x1 * wk.y;
        av[0][0] += x0 * wv.x; av[0][1] += x0 * wv.y;
        av[1][0] += x1 * wv.x; av[1][1] += x1 * wv.y;
    }
    const float scl = 0.35355339059327373f;   // 1/sqrt(8)
    float2 bq2 = *(const float2*)(bq + jc);
    float2 bk2 = *(const float2*)(bk + jc);
    float2 bv2 = *(const float2*)(bv + jc);
    const int h = jc >> 3, jj = jc & 7;
#pragma unroll
    for (int rr = 0; rr < 2; rr++) {
        int r = r0 + 2 * rg + rr;
        int b = r >> 9, s = r & 511;
        int base = ((b * NH + h) * SS + s) * 8 + jj;
        *(float2*)(g_q  + base) = make_float2((aq[rr][0] + bq2.x) * scl,
                                              (aq[rr][1] + bq2.y) * scl);
        *(float2*)(g_kk + base) = make_float2(ak[rr][0] + bk2.x, ak[rr][1] + bk2.y);
        *(float2*)(g_vv + base) = make_float2(av[rr][0] + bv2.x, av[rr][1] + bv2.y);
    }
}

// ---------------------------------------------------------------------------
// First launch: y = ytmp = x; qkv(x).  grid 256, block 128 (8 rows/block).
__global__ void __launch_bounds__(128) q0_kernel(
    const float* __restrict__ x,
    const float* __restrict__ Wq, const float* __restrict__ bq,
    const float* __restrict__ Wk, const float* __restrict__ bk,
    const float* __restrict__ Wv, const float* __restrict__ bv)
{
    __shared__ float sX[8 * 64];
    const int tid = threadIdx.x;
    const int lane = tid & 31, rg = tid >> 5;
    const int r0 = blockIdx.x * 8;
    // warp rg loads its own 2 rows (32 lanes x float4 = 512B)
    {
        int off = (r0 + 2 * rg) * 64;
        float4 v = ((const float4*)(x + off))[lane];
        ((float4*)(g_y + off))[lane] = v;
        ((float4*)(g_ytmp + off))[lane] = v;
        ((float4*)(sX + 2 * rg * 64))[lane] = v;
    }
    __syncwarp();
    qkv_phase(sX, r0, Wq, bq, Wk, bk, Wv, bv);
}

// ---------------------------------------------------------------------------
// Attention: block = (b,h, qtile of 64 queries), 256 threads, grid 256.
// 4 threads per query (key quarters on lane bits 3..4), shfl_xor merge.
__global__ void __launch_bounds__(256) attn_kernel()
{
    __shared__ float4 ks[SS * 2];
    __shared__ float4 vs[SS * 2];

    const int bh = blockIdx.x >> 3;
    const int qt = blockIdx.x & 7;
    const int tid = threadIdx.x;

    const float4* kg = (const float4*)g_kk + bh * SS * 2;
    const float4* vg = (const float4*)g_vv + bh * SS * 2;
    for (int i = tid; i < SS * 2; i += 256) { ks[i] = kg[i]; vs[i] = vg[i]; }
    __syncthreads();

    const int lane = tid & 31;
    const int warp = tid >> 5;
    const int quarter = lane >> 3;
    const int qg = qt * 64 + warp * 8 + (lane & 7);

    const float4* qp = (const float4*)g_q + (bh * SS + qg) * 2;
    const float4 q0 = qp[0];
    const float4 q1 = qp[1];

    float m = -1e30f, l = 0.f;
    float o[8];
#pragma unroll
    for (int j = 0; j < 8; j++) o[j] = 0.f;

    const int t0 = quarter * 128;
#pragma unroll 2
    for (int i = 0; i < 128; i++) {
        const int t = t0 + i;
        float4 ka = ks[2 * t], kb = ks[2 * t + 1];
        float s = q0.x * ka.x + q0.y * ka.y + q0.z * ka.z + q0.w * ka.w
                + q1.x * kb.x + q1.y * kb.y + q1.z * kb.z + q1.w * kb.w;
        if (s > m) {
            float corr = __expf(m - s);
            l *= corr;
#pragma unroll
            for (int j = 0; j < 8; j++) o[j] *= corr;
            m = s;
        }
        float p = __expf(s - m);
        l += p;
        float4 va = vs[2 * t], vb = vs[2 * t + 1];
        o[0] += p * va.x; o[1] += p * va.y; o[2] += p * va.z; o[3] += p * va.w;
        o[4] += p * vb.x; o[5] += p * vb.y; o[6] += p * vb.z; o[7] += p * vb.w;
    }

    // merge the 4 key-quarters (lanes l, l^8, l^16, l^24 share a query)
#pragma unroll
    for (int d = 8; d <= 16; d <<= 1) {
        float m2 = __shfl_xor_sync(0xffffffffu, m, d);
        float l2 = __shfl_xor_sync(0xffffffffu, l, d);
        float M  = fmaxf(m, m2);
        float sA = __expf(m - M);
        float sB = __expf(m2 - M);
        l = l * sA + l2 * sB;
#pragma unroll
        for (int j = 0; j < 8; j++) {
            float o2 = __shfl_xor_sync(0xffffffffu, o[j], d);
            o[j] = o[j] * sA + o2 * sB;
        }
        m = M;
    }

    if (quarter == 0) {
        float inv = 1.f / l;
        const int b = bh >> 3, h = bh & 7;
        float* dst = g_att + (b * SS + qg) * DD + h * 8;
        *(float4*)(dst)     = make_float4(o[0]*inv, o[1]*inv, o[2]*inv, o[3]*inv);
        *(float4*)(dst + 4) = make_float4(o[4]*inv, o[5]*inv, o[6]*inv, o[7]*inv);
    }
}

// ---------------------------------------------------------------------------
// Fused: out-proj + residual + FFN -> k[stage]; RK combo -> ytmp (or y);
// next-stage qkv.  All row-local; warp rg owns rows {2rg, 2rg+1}.
// grid 256, block 128 (8 rows/block).
__global__ void __launch_bounds__(128) fused_kernel(
    const float* __restrict__ Wo, const float* __restrict__ bo,
    const float* __restrict__ W1, const float* __restrict__ b1,
    const float* __restrict__ W2, const float* __restrict__ b2,
    const float* __restrict__ Wq, const float* __restrict__ bq,
    const float* __restrict__ Wk, const float* __restrict__ bk,
    const float* __restrict__ Wv, const float* __restrict__ bv,
    StageCtl ctl)
{
    __shared__ float sA[8 * 64];
    __shared__ float sH[8 * 64];
    __shared__ float sU[8 * 256];
    __shared__ float sX[8 * 64];

    const int tid = threadIdx.x;
    const int lane = tid & 31;
    const int rg = tid >> 5;            // warp id = row-group
    const int jc = lane * 2;            // 2 output cols
    const int r0 = blockIdx.x * 8;
    const int rA = r0 + 2 * rg;         // first of this warp's two rows

    // load att rows (warp-local)
    ((float4*)(sA + 2 * rg * 64))[lane] = ((const float4*)(g_att + rA * 64))[lane];
    __syncwarp();

    // ---- Phase B: out projection (Wo) + residual ----
    float o1[2][2] = {{0.f,0.f},{0.f,0.f}};
    {
        const float* a0 = sA + (2 * rg) * 64;
        const float* a1 = a0 + 64;
#pragma unroll 8
        for (int i = 0; i < 64; i++) {
            float2 w = __ldg((const float2*)(Wo + i * 64 + jc));
            float x0 = a0[i], x1 = a1[i];
            o1[0][0] += x0 * w.x; o1[0][1] += x0 * w.y;
            o1[1][0] += x1 * w.x; o1[1][1] += x1 * w.y;
        }
    }
    {
        float2 bo2 = *(const float2*)(bo + jc);
#pragma unroll
        for (int rr = 0; rr < 2; rr++) {
            o1[rr][0] += bo2.x; o1[rr][1] += bo2.y;
            float2 yt = *(const float2*)(g_ytmp + (rA + rr) * 64 + jc);
            sH[(2 * rg + rr) * 64 + jc]     = yt.x + o1[rr][0];
            sH[(2 * rg + rr) * 64 + jc + 1] = yt.y + o1[rr][1];
        }
    }
    __syncwarp();

    // ---- Phase C: hidden layer (W1) + relu ----
    {
        const int fc = lane * 8;   // 8 hidden cols per thread
        const float* h0 = sH + (2 * rg) * 64;
        const float* h1 = h0 + 64;
        float u[2][8];
#pragma unroll
        for (int rr = 0; rr < 2; rr++)
#pragma unroll
            for (int j = 0; j < 8; j++) u[rr][j] = 0.f;
#pragma unroll 4
        for (int i = 0; i < 64; i++) {
            float4 wa = __ldg((const float4*)(W1 + i * 256 + fc));
            float4 wb = __ldg((const float4*)(W1 + i * 256 + fc + 4));
            float hv0 = h0[i], hv1 = h1[i];
            u[0][0] += hv0 * wa.x; u[0][1] += hv0 * wa.y;
            u[0][2] += hv0 * wa.z; u[0][3] += hv0 * wa.w;
            u[0][4] += hv0 * wb.x; u[0][5] += hv0 * wb.y;
            u[0][6] += hv0 * wb.z; u[0][7] += hv0 * wb.w;
            u[1][0] += hv1 * wa.x; u[1][1] += hv1 * wa.y;
            u[1][2] += hv1 * wa.z; u[1][3] += hv1 * wa.w;
            u[1][4] += hv1 * wb.x; u[1][5] += hv1 * wb.y;
            u[1][6] += hv1 * wb.z; u[1][7] += hv1 * wb.w;
        }
        float4 ba = __ldg((const float4*)(b1 + fc));
        float4 bb = __ldg((const float4*)(b1 + fc + 4));
#pragma unroll
        for (int rr = 0; rr < 2; rr++) {
            float* up = sU + (2 * rg + rr) * 256 + fc;
            up[0] = fmaxf(u[rr][0] + ba.x, 0.f);
            up[1] = fmaxf(u[rr][1] + ba.y, 0.f);
            up[2] = fmaxf(u[rr][2] + ba.z, 0.f);
            up[3] = fmaxf(u[rr][3] + ba.w, 0.f);
            up[4] = fmaxf(u[rr][4] + bb.x, 0.f);
            up[5] = fmaxf(u[rr][5] + bb.y, 0.f);
            up[6] = fmaxf(u[rr][6] + bb.z, 0.f);
            up[7] = fmaxf(u[rr][7] + bb.w, 0.f);
        }
    }
    __syncwarp();

    // ---- Phase D: second FFN layer (W2); k_stage = att_proj + ffn ----
    float kv[2][2];
    {
        float f2[2][2] = {{0.f,0.f},{0.f,0.f}};
        const float* u0 = sU + (2 * rg) * 256;
        const float* u1 = u0 + 256;
#pragma unroll 8
        for (int i = 0; i < 256; i++) {
            float2 w = __ldg((const float2*)(W2 + i * 64 + jc));
            float v0 = u0[i], v1 = u1[i];
            f2[0][0] += v0 * w.x; f2[0][1] += v0 * w.y;
            f2[1][0] += v1 * w.x; f2[1][1] += v1 * w.y;
        }
        float2 b22 = *(const float2*)(b2 + jc);
#pragma unroll
        for (int rr = 0; rr < 2; rr++) {
            kv[rr][0] = o1[rr][0] + f2[rr][0] + b22.x;
            kv[rr][1] = o1[rr][1] + f2[rr][1] + b22.y;
            *(float2*)(g_kst + (ctl.stage * NROWS + rA + rr) * 64 + jc) =
                make_float2(kv[rr][0], kv[rr][1]);
        }
    }

    // ---- Phase E: RK combination -> ytmp (and optionally y) ----
#pragma unroll
    for (int rr = 0; rr < 2; rr++) {
        int r = rA + rr;
        float2 v = *(const float2*)(g_y + r * 64 + jc);
#pragma unroll 6
        for (int c = 0; c < 6; c++) {
            if (c < ctl.nc) {
                float kx, ky;
                if (c == ctl.stage) { kx = kv[rr][0]; ky = kv[rr][1]; }
                else {
                    float2 kc = *(const float2*)(g_kst + (c * NROWS + r) * 64 + jc);
                    kx = kc.x; ky = kc.y;
                }
                v.x += ctl.ac[c] * kx;
                v.y += ctl.ac[c] * ky;
            }
        }
        if (ctl.write_y) *(float2*)(g_y + r * 64 + jc) = v;
        *(float2*)(g_ytmp + r * 64 + jc) = v;
        sX[(2 * rg + rr) * 64 + jc]     = v.x;
        sX[(2 * rg + rr) * 64 + jc + 1] = v.y;
    }
    __syncwarp();

    // ---- Phase F: next-stage qkv ----
    if (ctl.do_qkv)
        qkv_phase(sX, r0, Wq, bq, Wk, bk, Wv, bv);
}

// ---------------------------------------------------------------------------
extern "C" void kernel_launch(void* const* d_in, const int* in_sizes, int n_in,
                              void* d_out, int out_size)
{
    (void)in_sizes; (void)n_in; (void)out_size;

    const float* x  = (const float*)d_in[0];
    // d_in[1] = mask: broadcasts over key axis -> softmax-invariant; ignored.
    const float* Wq = (const float*)d_in[2];
    const float* bq = (const float*)d_in[3];
    const float* Wk = (const float*)d_in[4];
    const float* bk = (const float*)d_in[5];
    const float* Wv = (const float*)d_in[6];
    const float* bv = (const float*)d_in[7];
    const float* Wo = (const float*)d_in[8];
    const float* bo = (const float*)d_in[9];
    const float* W1 = (const float*)d_in[10];
    const float* b1 = (const float*)d_in[11];
    const float* W2 = (const float*)d_in[12];
    const float* b2 = (const float*)d_in[13];

    static const double acoef[6][5] = {
        {0, 0, 0, 0, 0},
        {0.25, 0, 0, 0, 0},
        {3.0/32.0, 9.0/32.0, 0, 0, 0},
        {1932.0/2197.0, -7200.0/2197.0, 7296.0/2197.0, 0, 0},
        {439.0/216.0, -8.0, 3680.0/513.0, -845.0/4104.0, 0},
        {-8.0/27.0, 2.0, -3544.0/2565.0, 1859.0/4104.0, -11.0/40.0},
    };
    static const double bcoef[6] = {
        16.0/135.0, 0.0, 6656.0/12825.0, 28561.0/56430.0, -9.0/50.0, 2.0/55.0
    };

    q0_kernel<<<256, 128>>>(x, Wq, bq, Wk, bk, Wv, bv);

    for (int step = 0; step < 4; step++) {
        for (int st = 0; st < 6; st++) {
            attn_kernel<<<256, 256>>>();
            StageCtl ctl;
            ctl.stage = st;
            if (st < 5) {
                ctl.nc = st + 1;
                for (int c = 0; c < 6; c++)
                    ctl.ac[c] = (c <= st)
                        ? (float)((double)DT_F * acoef[st + 1][c]) : 0.f;
                ctl.do_qkv  = 1;
                ctl.write_y = 0;
            } else {
                ctl.nc = 6;
                for (int c = 0; c < 6; c++)
                    ctl.ac[c] = (float)((double)DT_F * bcoef[c]);
                ctl.write_y = 1;
                ctl.do_qkv  = (step < 3) ? 1 : 0;
            }
            fused_kernel<<<256, 128>>>(Wo, bo, W1, b1, W2, b2,
                                       Wq, bq, Wk, bk, Wv, bv, ctl);
        }
    }

    copy_out_kernel<<<128, 256>>>((float*)d_out);
}